// round 2
// baseline (speedup 1.0000x reference)
#include <cuda_runtime.h>
#include <math.h>

#define NTOK   2048
#define DMODEL 2048
#define KVD    512
#define NHEADS 16
#define HDIM   128

static __device__ float g_Q[NTOK * DMODEL];
static __device__ float g_K[NTOK * KVD];
static __device__ float g_V[NTOK * KVD];
static __device__ float g_S[(size_t)NHEADS * NTOK * NTOK];
static __device__ float g_C[NTOK * DMODEL];

// ---------------------------------------------------------------------------
// Generic 128x128 tile SGEMM body. BT=false: C = A(MxK) * B(KxN) (B row-major).
// BT=true : C = A(MxK) * B^T     (B stored NxK row-major).
// A is pre-offset to the tile's row start (col 0 of the K range),
// B is pre-offset to the tile's col start, C pre-offset to (brow, bcol).
// Requires Kdim % 8 == 0, 256 threads.
// ---------------------------------------------------------------------------
template <bool BT>
__device__ __forceinline__ void gemm128(const float* __restrict__ A,
                                        const float* __restrict__ B,
                                        float* __restrict__ C,
                                        int Kdim, int lda, int ldb, int ldc)
{
    __shared__ float As[8][128];
    __shared__ float Bs[8][128];
    const int tid  = threadIdx.x;
    const int arow = tid >> 1;          // 0..127
    const int acol = (tid & 1) << 2;    // 0 or 4
    const int brb  = tid >> 5;          // 0..7  (NN B row)
    const int bcb  = (tid & 31) << 2;   // 0..124 (NN B col)
    const int tx   = (tid & 15) << 3;
    const int ty   = (tid >> 4) << 3;

    float acc[8][8];
#pragma unroll
    for (int i = 0; i < 8; ++i)
#pragma unroll
        for (int j = 0; j < 8; ++j) acc[i][j] = 0.f;

    for (int k0 = 0; k0 < Kdim; k0 += 8) {
        float4 av = *reinterpret_cast<const float4*>(A + (size_t)arow * lda + k0 + acol);
        As[acol + 0][arow] = av.x;
        As[acol + 1][arow] = av.y;
        As[acol + 2][arow] = av.z;
        As[acol + 3][arow] = av.w;
        if (BT) {
            float4 bv = *reinterpret_cast<const float4*>(B + (size_t)arow * ldb + k0 + acol);
            Bs[acol + 0][arow] = bv.x;
            Bs[acol + 1][arow] = bv.y;
            Bs[acol + 2][arow] = bv.z;
            Bs[acol + 3][arow] = bv.w;
        } else {
            float4 bv = *reinterpret_cast<const float4*>(B + (size_t)(k0 + brb) * ldb + bcb);
            *reinterpret_cast<float4*>(&Bs[brb][bcb]) = bv;
        }
        __syncthreads();
#pragma unroll
        for (int k = 0; k < 8; ++k) {
            float ar[8], br[8];
#pragma unroll
            for (int i = 0; i < 8; ++i) ar[i] = As[k][ty + i];
#pragma unroll
            for (int j = 0; j < 8; ++j) br[j] = Bs[k][tx + j];
#pragma unroll
            for (int i = 0; i < 8; ++i)
#pragma unroll
                for (int j = 0; j < 8; ++j)
                    acc[i][j] = fmaf(ar[i], br[j], acc[i][j]);
        }
        __syncthreads();
    }
#pragma unroll
    for (int i = 0; i < 8; ++i)
#pragma unroll
        for (int j = 0; j < 8; j += 4) {
            float4 v = make_float4(acc[i][j], acc[i][j + 1], acc[i][j + 2], acc[i][j + 3]);
            *reinterpret_cast<float4*>(C + (size_t)(ty + i) * ldc + tx + j) = v;
        }
}

// ---- Q projection: g_Q = x @ Wq  (2048x2048 @ 2048x2048) --------------------
__global__ void proj_q_kernel(const float* __restrict__ X, const float* __restrict__ Wq)
{
    const int brow = blockIdx.y << 7, bcol = blockIdx.x << 7;
    gemm128<false>(X + (size_t)brow * DMODEL, Wq + bcol,
                   g_Q + (size_t)brow * DMODEL + bcol,
                   DMODEL, DMODEL, DMODEL, DMODEL);
}

// ---- K / V projections: grid.z selects which ------------------------------
__global__ void proj_kv_kernel(const float* __restrict__ X,
                               const float* __restrict__ Wk,
                               const float* __restrict__ Wv)
{
    const int brow = blockIdx.y << 7, bcol = blockIdx.x << 7;
    const float* W = (blockIdx.z == 0) ? Wk : Wv;
    float* O       = (blockIdx.z == 0) ? g_K : g_V;
    gemm128<false>(X + (size_t)brow * DMODEL, W + bcol,
                   O + (size_t)brow * KVD + bcol,
                   DMODEL, DMODEL, KVD, KVD);
}

// ---- RoPE (interleaved), in place on g_Q and g_K ---------------------------
__global__ void rope_kernel()
{
    int idx = blockIdx.x * blockDim.x + threadIdx.x;
    const int qpairs = NTOK * (DMODEL / 2);
    float* ptr;
    int t, p;
    if (idx < qpairs) {
        t = idx >> 10;                 // token (1024 pairs per token)
        int c = idx & 1023;            // pair column
        p = c & 63;                    // pair index within 128-dim head
        ptr = g_Q + (size_t)t * DMODEL + (c << 1);
    } else {
        idx -= qpairs;
        if (idx >= NTOK * (KVD / 2)) return;
        t = idx >> 8;                  // 256 pairs per token
        int c = idx & 255;
        p = c & 63;
        ptr = g_K + (size_t)t * KVD + (c << 1);
    }
    // inv_freq = 10000^(-p/64); compute in double, trig in fp32 (matches ref fp32 trig)
    double inv = exp(-(double)p * (9.210340371976184 / 64.0));
    float ang = (float)((double)t * inv);
    float cs = cosf(ang), sn = sinf(ang);
    float xe = ptr[0], xo = ptr[1];
    ptr[0] = xe * cs - xo * sn;
    ptr[1] = xe * sn + xo * cs;
}

// ---- scores: S[h] = Q_h @ K_h^T, skip fully-masked tiles -------------------
__global__ void qk_kernel()
{
    if (blockIdx.x > blockIdx.y) return;            // tile entirely above diagonal
    const int h    = blockIdx.z;
    const int brow = blockIdx.y << 7;               // query rows
    const int bcol = blockIdx.x << 7;               // key cols
    const int kvh = h >> 2, gs = h & 3;
    const float* A = g_Q + (size_t)brow * DMODEL + gs * 512 + kvh * 128;
    const float* B = g_K + (size_t)bcol * KVD + kvh * 128;
    float* C = g_S + (size_t)h * NTOK * NTOK + (size_t)brow * NTOK + bcol;
    gemm128<true>(A, B, C, HDIM, DMODEL, KVD, NTOK);
}

// ---- causal softmax over row i, zero-fill masked tail ----------------------
__global__ void softmax_kernel()
{
    const int i = blockIdx.x, h = blockIdx.y;
    float* row = g_S + (size_t)h * NTOK * NTOK + (size_t)i * NTOK;
    const int len = i + 1;
    const float scale = 0.08838834764831845f;       // 1/sqrt(128)
    __shared__ float red[8];
    const int tid = threadIdx.x;                    // 256 threads
    const int lane = tid & 31, wid = tid >> 5;

    float m = -1e30f;
    for (int j = tid; j < len; j += 256) m = fmaxf(m, row[j]);
#pragma unroll
    for (int o = 16; o; o >>= 1) m = fmaxf(m, __shfl_xor_sync(0xffffffffu, m, o));
    if (lane == 0) red[wid] = m;
    __syncthreads();
    m = red[0];
#pragma unroll
    for (int w = 1; w < 8; ++w) m = fmaxf(m, red[w]);
    __syncthreads();                                // everyone done reading red

    float s = 0.f;
    for (int j = tid; j < len; j += 256) {
        float e = expf((row[j] - m) * scale);
        row[j] = e;
        s += e;
    }
#pragma unroll
    for (int o = 16; o; o >>= 1) s += __shfl_xor_sync(0xffffffffu, s, o);
    if (lane == 0) red[wid] = s;
    __syncthreads();
    s = red[0];
#pragma unroll
    for (int w = 1; w < 8; ++w) s += red[w];
    const float invs = 1.f / s;

    for (int j = tid; j < len; j += 256) row[j] *= invs;
    for (int j = len + tid; j < NTOK; j += 256) row[j] = 0.f;   // masked tail -> 0
}

// ---- context: C_h = P_h @ V_h, K-loop truncated at causal limit ------------
__global__ void pv_kernel()
{
    const int h    = blockIdx.z;
    const int brow = blockIdx.y << 7;
    const int kvh  = h >> 2;
    const float* A = g_S + (size_t)h * NTOK * NTOK + (size_t)brow * NTOK;
    const float* B = g_V + kvh * 128;
    float* C = g_C + (size_t)brow * DMODEL + h * 128;   // output head order = kvh-major
    gemm128<false>(A, B, C, brow + 128 /*causal K cutoff*/, NTOK, KVD, DMODEL);
}

// ---- output projection: out = ctx @ Wo -------------------------------------
__global__ void out_kernel(const float* __restrict__ Wo, float* __restrict__ out)
{
    const int brow = blockIdx.y << 7, bcol = blockIdx.x << 7;
    gemm128<false>(g_C + (size_t)brow * DMODEL, Wo + bcol,
                   out + (size_t)brow * DMODEL + bcol,
                   DMODEL, DMODEL, DMODEL, DMODEL);
}

extern "C" void kernel_launch(void* const* d_in, const int* in_sizes, int n_in,
                              void* d_out, int out_size)
{
    (void)in_sizes; (void)n_in; (void)out_size;
    const float* x  = (const float*)d_in[0];
    const float* Wq = (const float*)d_in[1];
    const float* Wk = (const float*)d_in[2];
    const float* Wv = (const float*)d_in[3];
    const float* Wo = (const float*)d_in[4];
    float* out = (float*)d_out;

    proj_q_kernel<<<dim3(DMODEL / 128, NTOK / 128), 256>>>(x, Wq);
    proj_kv_kernel<<<dim3(KVD / 128, NTOK / 128, 2), 256>>>(x, Wk, Wv);

    const int total_pairs = NTOK * (DMODEL / 2) + NTOK * (KVD / 2);
    rope_kernel<<<(total_pairs + 255) / 256, 256>>>();

    qk_kernel<<<dim3(NTOK / 128, NTOK / 128, NHEADS), 256>>>();
    softmax_kernel<<<dim3(NTOK, NHEADS), 256>>>();
    pv_kernel<<<dim3(1, NTOK / 128, NHEADS), 256>>>();
    out_kernel<<<dim3(DMODEL / 128, NTOK / 128), 256>>>(Wo, out);
}

// round 3
// speedup vs baseline: 2.8154x; 2.8154x over previous
#include <cuda_runtime.h>
#include <math.h>
#include <stdint.h>

#define NTOK   2048
#define DMODEL 2048
#define KVD    512
#define NHEADS 16
#define HDIM   128

static __device__ float g_Q[NTOK * DMODEL];
static __device__ float g_K[NTOK * KVD];
static __device__ float g_V[NTOK * KVD];
static __device__ float g_S[(size_t)NHEADS * NTOK * NTOK];
static __device__ float g_C[NTOK * DMODEL];

__device__ __forceinline__ uint32_t f2tf32(float x) {
    uint32_t r;
    asm("cvt.rna.tf32.f32 %0, %1;" : "=r"(r) : "f"(x));
    return r;
}

__device__ __forceinline__ void mma_tf32(float c[4], const uint32_t a[4],
                                         uint32_t b0, uint32_t b1) {
    asm volatile(
        "mma.sync.aligned.m16n8k8.row.col.f32.tf32.tf32.f32 "
        "{%0,%1,%2,%3}, {%4,%5,%6,%7}, {%8,%9}, {%0,%1,%2,%3};"
        : "+f"(c[0]), "+f"(c[1]), "+f"(c[2]), "+f"(c[3])
        : "r"(a[0]), "r"(a[1]), "r"(a[2]), "r"(a[3]), "r"(b0), "r"(b1));
}

// ---------------------------------------------------------------------------
// TF32 tensor-core GEMM, 128x128 block tile, 256 threads (8 warps, 4m x 2n),
// warp tile 32x64, K chunk 32. BT=false: C = A(MxK) @ B(KxN), B row-major.
// BT=true:  C = A(MxK) @ B^T, B stored (NxK) row-major.
// A pre-offset to (block_row, k=0); B pre-offset to col/row block; C pre-offset.
// Requires Kdim % 32 == 0.
// ---------------------------------------------------------------------------
template <bool BT>
__device__ __forceinline__ void tf32gemm(const float* __restrict__ A,
                                         const float* __restrict__ B,
                                         float* __restrict__ C,
                                         int Kdim, int lda, int ldb, int ldc)
{
    __shared__ uint32_t As[128 * 36];                 // [m][k], pad 36: conflict-free
    __shared__ uint32_t Bs[BT ? (128 * 36) : (32 * 132)];
    const int tid  = threadIdx.x;
    const int lane = tid & 31, wid = tid >> 5;
    const int wm = wid & 3, wn = wid >> 2;
    const int g = lane >> 2, t = lane & 3;

    float acc[2][8][4];
#pragma unroll
    for (int mt = 0; mt < 2; ++mt)
#pragma unroll
        for (int nt = 0; nt < 8; ++nt)
#pragma unroll
            for (int j = 0; j < 4; ++j) acc[mt][nt][j] = 0.f;

    float4 areg[4], breg[4];

    // prologue: stage chunk 0
#pragma unroll
    for (int i = 0; i < 4; ++i) {
        int idx = tid + (i << 8);
        int r = idx >> 3, kk = (idx & 7) << 2;
        areg[i] = *reinterpret_cast<const float4*>(A + (size_t)r * lda + kk);
        if (BT) {
            breg[i] = *reinterpret_cast<const float4*>(B + (size_t)r * ldb + kk);
        } else {
            int rb = idx >> 5, n = (idx & 31) << 2;
            breg[i] = *reinterpret_cast<const float4*>(B + (size_t)rb * ldb + n);
        }
    }

    for (int k0 = 0; k0 < Kdim; k0 += 32) {
        // commit staged chunk to smem (tf32-converted)
#pragma unroll
        for (int i = 0; i < 4; ++i) {
            int idx = tid + (i << 8);
            int r = idx >> 3, kk = (idx & 7) << 2;
            As[r * 36 + kk + 0] = f2tf32(areg[i].x);
            As[r * 36 + kk + 1] = f2tf32(areg[i].y);
            As[r * 36 + kk + 2] = f2tf32(areg[i].z);
            As[r * 36 + kk + 3] = f2tf32(areg[i].w);
            if (BT) {
                Bs[r * 36 + kk + 0] = f2tf32(breg[i].x);
                Bs[r * 36 + kk + 1] = f2tf32(breg[i].y);
                Bs[r * 36 + kk + 2] = f2tf32(breg[i].z);
                Bs[r * 36 + kk + 3] = f2tf32(breg[i].w);
            } else {
                int rb = idx >> 5, n = (idx & 31) << 2;
                Bs[rb * 132 + n + 0] = f2tf32(breg[i].x);
                Bs[rb * 132 + n + 1] = f2tf32(breg[i].y);
                Bs[rb * 132 + n + 2] = f2tf32(breg[i].z);
                Bs[rb * 132 + n + 3] = f2tf32(breg[i].w);
            }
        }
        __syncthreads();

        // prefetch next chunk while computing this one
        if (k0 + 32 < Kdim) {
            const float* An = A + k0 + 32;
            const float* Bn = BT ? (B + k0 + 32) : (B + (size_t)(k0 + 32) * ldb);
#pragma unroll
            for (int i = 0; i < 4; ++i) {
                int idx = tid + (i << 8);
                int r = idx >> 3, kk = (idx & 7) << 2;
                areg[i] = *reinterpret_cast<const float4*>(An + (size_t)r * lda + kk);
                if (BT) {
                    breg[i] = *reinterpret_cast<const float4*>(Bn + (size_t)r * ldb + kk);
                } else {
                    int rb = idx >> 5, n = (idx & 31) << 2;
                    breg[i] = *reinterpret_cast<const float4*>(Bn + (size_t)rb * ldb + n);
                }
            }
        }

        // compute: 4 k-steps of 8
#pragma unroll
        for (int ks = 0; ks < 4; ++ks) {
            const int kb = ks << 3;
            uint32_t af[2][4];
#pragma unroll
            for (int mt = 0; mt < 2; ++mt) {
                int m = wm * 32 + mt * 16;
                af[mt][0] = As[(m + g) * 36 + kb + t];
                af[mt][1] = As[(m + g + 8) * 36 + kb + t];
                af[mt][2] = As[(m + g) * 36 + kb + t + 4];
                af[mt][3] = As[(m + g + 8) * 36 + kb + t + 4];
            }
#pragma unroll
            for (int nt = 0; nt < 8; ++nt) {
                int n = wn * 64 + nt * 8;
                uint32_t b0, b1;
                if (BT) {
                    b0 = Bs[(n + g) * 36 + kb + t];
                    b1 = Bs[(n + g) * 36 + kb + t + 4];
                } else {
                    b0 = Bs[(kb + t) * 132 + n + g];
                    b1 = Bs[(kb + t + 4) * 132 + n + g];
                }
                mma_tf32(acc[0][nt], af[0], b0, b1);
                mma_tf32(acc[1][nt], af[1], b0, b1);
            }
        }
        __syncthreads();
    }

    // epilogue
#pragma unroll
    for (int mt = 0; mt < 2; ++mt)
#pragma unroll
        for (int nt = 0; nt < 8; ++nt) {
            int row = wm * 32 + mt * 16 + g;
            int col = wn * 64 + nt * 8 + (t << 1);
            *reinterpret_cast<float2*>(C + (size_t)row * ldc + col) =
                make_float2(acc[mt][nt][0], acc[mt][nt][1]);
            *reinterpret_cast<float2*>(C + (size_t)(row + 8) * ldc + col) =
                make_float2(acc[mt][nt][2], acc[mt][nt][3]);
        }
}

// ---- Q projection ----------------------------------------------------------
__global__ void __launch_bounds__(256, 2)
proj_q_kernel(const float* __restrict__ X, const float* __restrict__ Wq)
{
    const int brow = blockIdx.y << 7, bcol = blockIdx.x << 7;
    tf32gemm<false>(X + (size_t)brow * DMODEL, Wq + bcol,
                    g_Q + (size_t)brow * DMODEL + bcol,
                    DMODEL, DMODEL, DMODEL, DMODEL);
}

// ---- K / V projections -----------------------------------------------------
__global__ void __launch_bounds__(256, 2)
proj_kv_kernel(const float* __restrict__ X,
               const float* __restrict__ Wk,
               const float* __restrict__ Wv)
{
    const int brow = blockIdx.y << 7, bcol = blockIdx.x << 7;
    const float* W = (blockIdx.z == 0) ? Wk : Wv;
    float* O       = (blockIdx.z == 0) ? g_K : g_V;
    tf32gemm<false>(X + (size_t)brow * DMODEL, W + bcol,
                    O + (size_t)brow * KVD + bcol,
                    DMODEL, DMODEL, KVD, KVD);
}

// ---- RoPE (interleaved), in place on g_Q and g_K ---------------------------
__global__ void rope_kernel()
{
    int idx = blockIdx.x * blockDim.x + threadIdx.x;
    const int qpairs = NTOK * (DMODEL / 2);
    float* ptr;
    int t, p;
    if (idx < qpairs) {
        t = idx >> 10;
        int c = idx & 1023;
        p = c & 63;
        ptr = g_Q + (size_t)t * DMODEL + (c << 1);
    } else {
        idx -= qpairs;
        if (idx >= NTOK * (KVD / 2)) return;
        t = idx >> 8;
        int c = idx & 255;
        p = c & 63;
        ptr = g_K + (size_t)t * KVD + (c << 1);
    }
    double inv = exp(-(double)p * (9.210340371976184 / 64.0));
    float ang = (float)((double)t * inv);
    float cs = cosf(ang), sn = sinf(ang);
    float xe = ptr[0], xo = ptr[1];
    ptr[0] = xe * cs - xo * sn;
    ptr[1] = xe * sn + xo * cs;
}

// ---- scores: S[h] = Q_h @ K_h^T (tf32), skip masked tiles ------------------
__global__ void __launch_bounds__(256, 2)
qk_kernel()
{
    if (blockIdx.x > blockIdx.y) return;
    const int h    = blockIdx.z;
    const int brow = blockIdx.y << 7;
    const int bcol = blockIdx.x << 7;
    const int kvh = h >> 2, gs = h & 3;
    const float* A = g_Q + (size_t)brow * DMODEL + gs * 512 + kvh * 128;
    const float* B = g_K + (size_t)bcol * KVD + kvh * 128;
    float* C = g_S + (size_t)h * NTOK * NTOK + (size_t)brow * NTOK + bcol;
    tf32gemm<true>(A, B, C, HDIM, DMODEL, KVD, NTOK);
}

// ---- causal softmax: single global read (8 vals/thread in regs) ------------
__global__ void __launch_bounds__(256)
softmax_kernel()
{
    const int i = blockIdx.x, h = blockIdx.y;
    float* row = g_S + (size_t)h * NTOK * NTOK + (size_t)i * NTOK;
    const int len = i + 1;
    const float scale = 0.08838834764831845f;       // 1/sqrt(128)
    __shared__ float red[8];
    const int tid = threadIdx.x;
    const int lane = tid & 31, wid = tid >> 5;

    float v[8];
#pragma unroll
    for (int w = 0; w < 8; ++w) {
        int j = tid + (w << 8);
        v[w] = (j < len) ? row[j] : -1e30f;
    }
    float m = -1e30f;
#pragma unroll
    for (int w = 0; w < 8; ++w) m = fmaxf(m, v[w]);
#pragma unroll
    for (int o = 16; o; o >>= 1) m = fmaxf(m, __shfl_xor_sync(0xffffffffu, m, o));
    if (lane == 0) red[wid] = m;
    __syncthreads();
    m = red[0];
#pragma unroll
    for (int w = 1; w < 8; ++w) m = fmaxf(m, red[w]);
    __syncthreads();

    float s = 0.f;
#pragma unroll
    for (int w = 0; w < 8; ++w) {
        int j = tid + (w << 8);
        float e = (j < len) ? expf((v[w] - m) * scale) : 0.f;
        v[w] = e;
        s += e;
    }
#pragma unroll
    for (int o = 16; o; o >>= 1) s += __shfl_xor_sync(0xffffffffu, s, o);
    if (lane == 0) red[wid] = s;
    __syncthreads();
    s = red[0];
#pragma unroll
    for (int w = 1; w < 8; ++w) s += red[w];
    const float invs = 1.f / s;

#pragma unroll
    for (int w = 0; w < 8; ++w) {
        int j = tid + (w << 8);
        row[j] = (j < len) ? v[w] * invs : 0.f;     // zero masked tail
    }
}

// ---- context: C_h = P_h @ V_h, K truncated at causal limit -----------------
__global__ void __launch_bounds__(256, 2)
pv_kernel()
{
    const int h    = blockIdx.z;
    const int brow = blockIdx.y << 7;
    const int kvh  = h >> 2;
    const float* A = g_S + (size_t)h * NTOK * NTOK + (size_t)brow * NTOK;
    const float* B = g_V + kvh * 128;
    float* C = g_C + (size_t)brow * DMODEL + h * 128;
    tf32gemm<false>(A, B, C, brow + 128, NTOK, KVD, DMODEL);
}

// ---- output projection: out = ctx @ Wo -------------------------------------
__global__ void __launch_bounds__(256, 2)
out_kernel(const float* __restrict__ Wo, float* __restrict__ out)
{
    const int brow = blockIdx.y << 7, bcol = blockIdx.x << 7;
    tf32gemm<false>(g_C + (size_t)brow * DMODEL, Wo + bcol,
                    out + (size_t)brow * DMODEL + bcol,
                    DMODEL, DMODEL, DMODEL, DMODEL);
}

extern "C" void kernel_launch(void* const* d_in, const int* in_sizes, int n_in,
                              void* d_out, int out_size)
{
    (void)in_sizes; (void)n_in; (void)out_size;
    const float* x  = (const float*)d_in[0];
    const float* Wq = (const float*)d_in[1];
    const float* Wk = (const float*)d_in[2];
    const float* Wv = (const float*)d_in[3];
    const float* Wo = (const float*)d_in[4];
    float* out = (float*)d_out;

    proj_q_kernel<<<dim3(DMODEL / 128, NTOK / 128), 256>>>(x, Wq);
    proj_kv_kernel<<<dim3(KVD / 128, NTOK / 128, 2), 256>>>(x, Wk, Wv);

    const int total_pairs = NTOK * (DMODEL / 2) + NTOK * (KVD / 2);
    rope_kernel<<<(total_pairs + 255) / 256, 256>>>();

    qk_kernel<<<dim3(NTOK / 128, NTOK / 128, NHEADS), 256>>>();
    softmax_kernel<<<dim3(NTOK, NHEADS), 256>>>();
    pv_kernel<<<dim3(1, NTOK / 128, NHEADS), 256>>>();
    out_kernel<<<dim3(DMODEL / 128, NTOK / 128), 256>>>(Wo, out);
}